// round 13
// baseline (speedup 1.0000x reference)
#include <cuda_runtime.h>
#include <cuda_bf16.h>
#include <cuda_fp16.h>
#include <math.h>

#define MAXN 100000
#define MAXE 1600000

// ---------------- device scratch ----------------
__device__ uint2  g_embh[MAXN * 32];  // gathered emb rows, fp16 (128/node)
__device__ uint2  g_h1h[MAXN * 32];   // layer1 features, fp16x4 per uint2 (128/node)
__device__ uint2  g_x2h[MAXN * 32];   // layer1 output (fp16), layer2 GEMM input
__device__ uint2  g_h2h[MAXN * 16];   // layer2 pre-agg features, fp16x4 (64/node)
__device__ __align__(16) __half g_w1t[128 * 128];  // W1^T fp16 (n-major)
__device__ __align__(16) __half g_w2t[64 * 128];   // W2^T fp16 (n-major)
__device__ float g_as1[MAXN * 4];
__device__ float g_ad1[MAXN * 4];
__device__ float g_as2p[MAXN * 2];    // layer2 src-logit partials (per warp-half)
__device__ float g_ad2p[MAXN * 2];
__device__ int   g_srcb[MAXE];
__device__ int   g_dstb[MAXE];
__device__ int   g_deg[MAXN];         // zeroed by k_scan after reading (replay-safe)
__device__ int   g_off[MAXN + 1];
__device__ int   g_cur[MAXN];
__device__ int   g_csr[MAXE];
__device__ unsigned long long g_lb[512];

__device__ __forceinline__ bool sniff64(const int* xw) { return xw[1] == 0; }

// 16B-chunk swizzle: row-local XOR keeps ldmatrix column reads conflict-free.
__device__ __forceinline__ int swz(int row, int ch) {
    return (row * 16 + (ch ^ (row & 15))) << 4;   // byte offset
}

__device__ __forceinline__ void ldsm4(unsigned& r0, unsigned& r1,
                                      unsigned& r2, unsigned& r3, unsigned addr) {
    asm volatile("ldmatrix.sync.aligned.m8n8.x4.shared.b16 {%0,%1,%2,%3}, [%4];"
                 : "=r"(r0), "=r"(r1), "=r"(r2), "=r"(r3) : "r"(addr));
}
__device__ __forceinline__ void mma16816(float* c, unsigned a0, unsigned a1,
                                         unsigned a2, unsigned a3,
                                         unsigned b0, unsigned b1) {
    asm volatile(
        "mma.sync.aligned.m16n8k16.row.col.f32.f16.f16.f32 "
        "{%0,%1,%2,%3}, {%4,%5,%6,%7}, {%8,%9}, {%0,%1,%2,%3};"
        : "+f"(c[0]), "+f"(c[1]), "+f"(c[2]), "+f"(c[3])
        : "r"(a0), "r"(a1), "r"(a2), "r"(a3), "r"(b0), "r"(b1));
}
__device__ __forceinline__ void cpa16(unsigned dst, const void* src) {
    asm volatile("cp.async.cg.shared.global [%0], [%1], 16;"
                 :: "r"(dst), "l"(src));
}
__device__ __forceinline__ void cpa_wait() {
    asm volatile("cp.async.commit_group;");
    asm volatile("cp.async.wait_group 0;" ::: "memory");
}

// ------- merged conversion kernel: 3 block roles -------
// [0, nb)          : lb reset + W1/W2 transpose->fp16
// [nb, nb+cb)      : emb gather -> fp16 (warp per node)
// [nb+cb, ...)     : ei conversion + degree histogram (deg pre-zeroed by k_scan)
__global__ void k_conv(const void* __restrict__ xidx,
                       const float* __restrict__ W1,
                       const float* __restrict__ W2,
                       const float* __restrict__ emb,
                       const void* __restrict__ ei,
                       int n, int e, int nb, int cb) {
    int b = blockIdx.x;
    if (b < nb) {
        int i = b * 256 + threadIdx.x;
        if (i < 512) g_lb[i] = 0ull;
        if (i < 128 * 128) {
            int nn = i >> 7, k = i & 127;
            g_w1t[i] = __float2half(W1[k * 128 + nn]);
        }
        if (i < 64 * 128) {
            int nn = i >> 7, k = i & 127;
            g_w2t[i] = __float2half(W2[k * 64 + nn]);
        }
        return;
    }
    if (b < nb + cb) {
        int node = (b - nb) * 8 + (threadIdx.x >> 5);
        int lane = threadIdx.x & 31;
        if (node >= n) return;
        bool is64 = sniff64((const int*)xidx);
        long long g = is64 ? ((const long long*)xidx)[node]
                           : (long long)((const int*)xidx)[node];
        float4 x = ((const float4*)emb)[g * 32 + lane];
        __half2 h0 = __float22half2_rn(make_float2(x.x, x.y));
        __half2 h1 = __float22half2_rn(make_float2(x.z, x.w));
        g_embh[node * 32 + lane] = make_uint2(*(unsigned*)&h0, *(unsigned*)&h1);
        return;
    }
    int i = (b - nb - cb) * 256 + threadIdx.x;
    if (i >= e) return;
    bool is64 = sniff64((const int*)xidx);
    int s, d;
    if (is64) {
        s = (int)((const long long*)ei)[i];
        d = (int)((const long long*)ei)[(long long)e + i];
    } else {
        s = ((const int*)ei)[i];
        d = ((const int*)ei)[e + i];
    }
    g_srcb[i] = s;
    g_dstb[i] = d;
    atomicAdd(&g_deg[d], 1);
}

// ---------------- single-pass scan, warp-parallel decoupled lookback ----------------
// Also resets g_deg to zero after reading (prepares next graph replay).
__global__ void k_scan(int n, int etot) {
    __shared__ int s[256];
    __shared__ int s_prefix;
    int tid = threadIdx.x;
    int b = blockIdx.x;
    int i = b * 256 + tid;
    int v = (i < n) ? g_deg[i] : 0;
    s[tid] = v;
    __syncthreads();
    for (int o = 1; o < 256; o <<= 1) {
        int t = 0;
        if (tid >= o) t = s[tid - o];
        __syncthreads();
        s[tid] += t;
        __syncthreads();
    }
    int incl = s[tid];
    int agg = s[255];

    if (tid < 32) {
        if (tid == 0) {
            unsigned long long pub = (b == 0)
                ? ((2ull << 32) | (unsigned)agg)
                : ((1ull << 32) | (unsigned)agg);
            __threadfence();
            atomicExch(&g_lb[b], pub);
        }
        int ex = 0;
        if (b > 0) {
            int p = b - 1;
            while (true) {
                int idx = p - (int)tid;
                unsigned long long st = (idx >= 0) ? atomicAdd(&g_lb[idx], 0ull)
                                                   : (2ull << 32);
                unsigned flag = (unsigned)(st >> 32);
                if (__any_sync(0xffffffffu, flag == 0u)) continue;
                unsigned m2 = __ballot_sync(0xffffffffu, flag == 2u);
                int contrib;
                if (m2) {
                    int L = __ffs(m2) - 1;
                    contrib = ((int)tid <= L) ? (int)(unsigned)st : 0;
                } else {
                    contrib = (int)(unsigned)st;
                }
#pragma unroll
                for (int o = 16; o > 0; o >>= 1)
                    contrib += __shfl_xor_sync(0xffffffffu, contrib, o);
                ex += contrib;
                if (m2) break;
                p -= 32;
            }
            if (tid == 0) {
                __threadfence();
                atomicExch(&g_lb[b], (2ull << 32) | (unsigned)(ex + agg));
            }
        }
        if (tid == 0) s_prefix = ex;
    }
    __syncthreads();
    int ex = s_prefix;
    if (i < n) {
        int o = ex + incl - v;
        g_off[i] = o;
        g_cur[i] = o;
        g_deg[i] = 0;                       // reset for next replay
        if (i == n - 1) g_off[n] = etot;
    }
}

// ---------------- tensor-core GEMM, cp.async staging, fragment-direct epilogue -----
// Block = 64 nodes, 256 threads. Warp = m16 x nCOLS/2 tile. K = 128. A source fp16.
// LAYER 1: GEMM and CSR-scatter blocks INTERLEAVED (even/odd).
template <int LAYER>
__global__ void __launch_bounds__(256, 4) k_gemm(const float* __restrict__ asrc,
                                                 const float* __restrict__ adst,
                                                 int n, int gb, int sb, int e) {
    int gemm_idx = blockIdx.x;
    if (LAYER == 1) {
        int bid = blockIdx.x;
        int mn = (gb < sb) ? gb : sb;
        int both = 2 * mn;
        bool isc;
        int ridx;
        if (bid < both) {
            isc = (bid & 1);
            ridx = bid >> 1;
        } else if (gb >= sb) {
            isc = false;
            ridx = bid - both + mn;
        } else {
            isc = true;
            ridx = bid - both + mn;
        }
        if (isc) {
            int start = ridx * 1024 + threadIdx.x;
#pragma unroll
            for (int k = 0; k < 4; k++) {
                int i = start + k * 256;
                if (i < e) {
                    int pos = atomicAdd(&g_cur[g_dstb[i]], 1);
                    g_csr[pos] = g_srcb[i];
                }
            }
            return;
        }
        gemm_idx = ridx;
    }

    constexpr int COLS = (LAYER == 1) ? 128 : 64;
    constexpr int NT2 = COLS / 16;          // n-tiles per warp: 8 / 4
    constexpr int SBYTES = 16384 + COLS * 256;

    __shared__ __align__(16) char sbuf[SBYTES];
    char* Ab = sbuf;
    char* Bb = sbuf + 16384;

    const int tid = threadIdx.x;
    const int lane = tid & 31;
    const int wid = tid >> 5;
    const int base = gemm_idx * 64;

    unsigned a_u = (unsigned)__cvta_generic_to_shared(Ab);
    unsigned b_u = (unsigned)__cvta_generic_to_shared(Bb);

    // ---- stage A (fp16 node rows, cp.async) ----
    const uint2* Asrc = (LAYER == 1) ? g_embh : g_x2h;
#pragma unroll 4
    for (int idx = tid; idx < 64 * 16; idx += 256) {
        int r = idx >> 4, ch = idx & 15;
        int node = base + r;
        if (node < n) cpa16(a_u + swz(r, ch), Asrc + node * 32 + ch * 2);
        else *(uint4*)(Ab + swz(r, ch)) = make_uint4(0, 0, 0, 0);
    }
    // ---- stage B = W^T (cp.async) ----
    {
        const uint4* Wt = (const uint4*)((LAYER == 1) ? g_w1t : g_w2t);
#pragma unroll 4
        for (int idx = tid; idx < COLS * 16; idx += 256) {
            int r = idx >> 4, ch = idx & 15;
            cpa16(b_u + swz(r, ch), Wt + r * 16 + ch);
        }
    }
    cpa_wait();
    __syncthreads();

    // ---- mma mainloop: warp = m16 (mw) x n-half (nh) ----
    const int mw = wid >> 1;
    const int nh = wid & 1;
    const int m0 = mw * 16;

    float c[NT2][4];
#pragma unroll
    for (int j = 0; j < NT2; j++)
#pragma unroll
        for (int q = 0; q < 4; q++) c[j][q] = 0.f;

    const int tl = lane >> 3;
    const int rr = lane & 7;

#pragma unroll
    for (int s = 0; s < 8; s++) {
        int chunk = 2 * s + (tl >> 1);
        unsigned a0, a1, a2, a3;
        ldsm4(a0, a1, a2, a3, a_u + swz(m0 + (tl & 1) * 8 + rr, chunk));
#pragma unroll
        for (int t = 0; t < NT2 / 2; t++) {
            int brow = nh * (NT2 * 8) + t * 16;
            unsigned r0, r1, r2, r3;
            ldsm4(r0, r1, r2, r3, b_u + swz(brow + (tl & 1) * 8 + rr, chunk));
            mma16816(c[2 * t], a0, a1, a2, a3, r0, r2);
            mma16816(c[2 * t + 1], a0, a1, a2, a3, r1, r3);
        }
    }

    // ---- fragment-direct epilogue: logit partials + fp16 stores, no smem ----
    const int g = lane >> 2;
    const int tg = lane & 3;
    const int colbase = nh * (NT2 * 8);     // 0/64 (L1), 0/32 (L2)
    const int node0 = base + m0 + g;
    const int node1 = node0 + 8;

    if (LAYER == 1) {
        // warp half covers 2 complete heads (cols colbase..colbase+63)
        float s0a = 0.f, s0b = 0.f, d0a = 0.f, d0b = 0.f;   // row g
        float s1a = 0.f, s1b = 0.f, d1a = 0.f, d1b = 0.f;   // row g+8
#pragma unroll
        for (int j = 0; j < 8; j++) {
            int col = colbase + j * 8 + 2 * tg;
            float2 as = __ldg((const float2*)(asrc + col));
            float2 ad = __ldg((const float2*)(adst + col));
            float ps0 = c[j][0] * as.x + c[j][1] * as.y;
            float pd0 = c[j][0] * ad.x + c[j][1] * ad.y;
            float ps1 = c[j][2] * as.x + c[j][3] * as.y;
            float pd1 = c[j][2] * ad.x + c[j][3] * ad.y;
            if (j < 4) { s0a += ps0; d0a += pd0; s1a += ps1; d1a += pd1; }
            else       { s0b += ps0; d0b += pd0; s1b += ps1; d1b += pd1; }
        }
#pragma unroll
        for (int o = 1; o < 4; o <<= 1) {
            s0a += __shfl_xor_sync(0xffffffffu, s0a, o);
            s0b += __shfl_xor_sync(0xffffffffu, s0b, o);
            d0a += __shfl_xor_sync(0xffffffffu, d0a, o);
            d0b += __shfl_xor_sync(0xffffffffu, d0b, o);
            s1a += __shfl_xor_sync(0xffffffffu, s1a, o);
            s1b += __shfl_xor_sync(0xffffffffu, s1b, o);
            d1a += __shfl_xor_sync(0xffffffffu, d1a, o);
            d1b += __shfl_xor_sync(0xffffffffu, d1b, o);
        }
        int h0i = 2 * nh, h1i = 2 * nh + 1;
        if (tg == 0) {
            if (node0 < n) {
                g_as1[node0 * 4 + h0i] = s0a; g_as1[node0 * 4 + h1i] = s0b;
                g_ad1[node0 * 4 + h0i] = d0a; g_ad1[node0 * 4 + h1i] = d0b;
            }
            if (node1 < n) {
                g_as1[node1 * 4 + h0i] = s1a; g_as1[node1 * 4 + h1i] = s1b;
                g_ad1[node1 * 4 + h0i] = d1a; g_ad1[node1 * 4 + h1i] = d1b;
            }
        }
        unsigned* H = (unsigned*)g_h1h;     // node*64 unsigneds (half2 each)
#pragma unroll
        for (int j = 0; j < 8; j++) {
            int ci = (colbase >> 1) + j * 4 + tg;
            __half2 h0 = __float22half2_rn(make_float2(c[j][0], c[j][1]));
            __half2 h1 = __float22half2_rn(make_float2(c[j][2], c[j][3]));
            if (node0 < n) H[node0 * 64 + ci] = *(unsigned*)&h0;
            if (node1 < n) H[node1 * 64 + ci] = *(unsigned*)&h1;
        }
    } else {
        // single head spans both halves: store per-half partials
        float s0 = 0.f, d0 = 0.f, s1 = 0.f, d1 = 0.f;
#pragma unroll
        for (int j = 0; j < 4; j++) {
            int col = colbase + j * 8 + 2 * tg;
            float2 as = __ldg((const float2*)(asrc + col));
            float2 ad = __ldg((const float2*)(adst + col));
            s0 += c[j][0] * as.x + c[j][1] * as.y;
            d0 += c[j][0] * ad.x + c[j][1] * ad.y;
            s1 += c[j][2] * as.x + c[j][3] * as.y;
            d1 += c[j][2] * ad.x + c[j][3] * ad.y;
        }
#pragma unroll
        for (int o = 1; o < 4; o <<= 1) {
            s0 += __shfl_xor_sync(0xffffffffu, s0, o);
            d0 += __shfl_xor_sync(0xffffffffu, d0, o);
            s1 += __shfl_xor_sync(0xffffffffu, s1, o);
            d1 += __shfl_xor_sync(0xffffffffu, d1, o);
        }
        if (tg == 0) {
            if (node0 < n) { g_as2p[node0 * 2 + nh] = s0; g_ad2p[node0 * 2 + nh] = d0; }
            if (node1 < n) { g_as2p[node1 * 2 + nh] = s1; g_ad2p[node1 * 2 + nh] = d1; }
        }
        unsigned* H = (unsigned*)g_h2h;     // node*32 unsigneds
#pragma unroll
        for (int j = 0; j < 4; j++) {
            int ci = (colbase >> 1) + j * 4 + tg;
            __half2 h0 = __float22half2_rn(make_float2(c[j][0], c[j][1]));
            __half2 h1 = __float22half2_rn(make_float2(c[j][2], c[j][3]));
            if (node0 < n) H[node0 * 32 + ci] = *(unsigned*)&h0;
            if (node1 < n) H[node1 * 32 + ci] = *(unsigned*)&h1;
        }
    }
}

__device__ __forceinline__ float att_w(float e) {
    float lr = (e > 0.f) ? e : 0.2f * e;
    return __expf(lr);
}

// ---------------- fused gather layer 1 (fp16): softmax-agg + bias + ELU -> fp16 x2 ----
__global__ void k_gather1(const float* __restrict__ b1, int n) {
    int node = (blockIdx.x * blockDim.x + threadIdx.x) >> 5;
    int lane = threadIdx.x & 31;
    if (node >= n) return;
    int head = lane >> 3;

    float ad = g_ad1[node * 4 + head];

    float w = att_w(g_as1[node * 4 + head] + ad);
    uint2 p = g_h1h[node * 32 + lane];
    float2 f0 = __half22float2(*(const __half2*)&p.x);
    float2 f1 = __half22float2(*(const __half2*)&p.y);
    float4 acc = make_float4(w * f0.x, w * f0.y, w * f1.x, w * f1.y);
    float wsum = w;

    int i = g_off[node];
    int iend = g_off[node + 1];
    for (; i < iend; i++) {
        int src = g_csr[i];
        float ww = att_w(g_as1[src * 4 + head] + ad);
        uint2 q = g_h1h[src * 32 + lane];
        float2 v0 = __half22float2(*(const __half2*)&q.x);
        float2 v1 = __half22float2(*(const __half2*)&q.y);
        acc.x += ww * v0.x;
        acc.y += ww * v0.y;
        acc.z += ww * v1.x;
        acc.w += ww * v1.y;
        wsum += ww;
    }
    float inv = 1.f / wsum;
    float4 bb = ((const float4*)b1)[lane];
    float ox = acc.x * inv + bb.x;
    float oy = acc.y * inv + bb.y;
    float oz = acc.z * inv + bb.z;
    float ow = acc.w * inv + bb.w;
    ox = (ox > 0.f) ? ox : expm1f(ox);
    oy = (oy > 0.f) ? oy : expm1f(oy);
    oz = (oz > 0.f) ? oz : expm1f(oz);
    ow = (ow > 0.f) ? ow : expm1f(ow);
    __half2 h0 = __float22half2_rn(make_float2(ox, oy));
    __half2 h1 = __float22half2_rn(make_float2(oz, ow));
    g_x2h[node * 32 + lane] = make_uint2(*(unsigned*)&h0, *(unsigned*)&h1);
}

// ---------------- fused gather layer 2 (fp16): softmax-agg + bias ----------------
__global__ void k_gather2(const float* __restrict__ b2, float* __restrict__ out, int n) {
    int node = (blockIdx.x * blockDim.x + threadIdx.x) >> 5;
    int lane = threadIdx.x & 31;
    if (node >= n) return;

    const __half2* H2 = (const __half2*)g_h2h;
    float2 pd = ((const float2*)g_ad2p)[node];
    float ad = pd.x + pd.y;
    float2 ps = ((const float2*)g_as2p)[node];

    float w = att_w(ps.x + ps.y + ad);
    float2 hv = __half22float2(H2[node * 32 + lane]);
    float2 acc = make_float2(w * hv.x, w * hv.y);
    float wsum = w;

    int i = g_off[node];
    int iend = g_off[node + 1];
    for (; i < iend; i++) {
        int src = g_csr[i];
        float2 qs = ((const float2*)g_as2p)[src];
        float ww = att_w(qs.x + qs.y + ad);
        float2 v = __half22float2(H2[src * 32 + lane]);
        acc.x += ww * v.x;
        acc.y += ww * v.y;
        wsum += ww;
    }
    float inv = 1.f / wsum;
    float2 bb = ((const float2*)b2)[lane];
    ((float2*)out)[node * 32 + lane] =
        make_float2(acc.x * inv + bb.x, acc.y * inv + bb.y);
}

// ---------------- launch ----------------
extern "C" void kernel_launch(void* const* d_in, const int* in_sizes, int n_in,
                              void* d_out, int out_size) {
    const void* xidx = d_in[0];
    const void* ei = d_in[1];
    const float* emb = (const float*)d_in[2];
    const float* W1 = (const float*)d_in[3];
    const float* a_src1 = (const float*)d_in[4];
    const float* a_dst1 = (const float*)d_in[5];
    const float* b1 = (const float*)d_in[6];
    const float* W2 = (const float*)d_in[7];
    const float* a_src2 = (const float*)d_in[8];
    const float* a_dst2 = (const float*)d_in[9];
    const float* b2 = (const float*)d_in[10];
    float* out = (float*)d_out;

    int n = in_sizes[0];
    int e = in_sizes[1] / 2;

    int nb256 = (n + 255) / 256;
    int eb256 = (e + 255) / 256;
    int nwarp = (n + 7) / 8;
    int gb = (n + 63) / 64;
    int sb = (e + 1023) / 1024;   // scatter blocks: 256 thr x 4 edges
    int cb = (n + 7) / 8;         // emb-convert blocks: 8 warps/block, warp/node

    k_conv<<<nb256 + cb + eb256, 256>>>(xidx, W1, W2, emb, ei, n, e, nb256, cb);
    k_scan<<<nb256, 256>>>(n, e);

    k_gemm<1><<<gb + sb, 256>>>(a_src1, a_dst1, n, gb, sb, e);
    k_gather1<<<nwarp, 256>>>(b1, n);

    k_gemm<2><<<gb, 256>>>(a_src2, a_dst2, n, gb, 0, 0);
    k_gather2<<<nwarp, 256>>>(b2, out, n);
}

// round 14
// speedup vs baseline: 1.0409x; 1.0409x over previous
#include <cuda_runtime.h>
#include <cuda_bf16.h>
#include <cuda_fp16.h>
#include <math.h>

#define MAXN 100000
#define MAXE 1600000

// ---------------- device scratch ----------------
__device__ uint2  g_embh[MAXN * 32];  // gathered emb rows, fp16 (128/node)
__device__ uint2  g_h1h[MAXN * 32];   // layer1 features, fp16x4 per uint2 (128/node)
__device__ uint2  g_x2h[MAXN * 32];   // layer1 output (fp16), layer2 GEMM input
__device__ uint2  g_h2h[MAXN * 16];   // layer2 pre-agg features, fp16x4 (64/node)
__device__ __align__(16) __half g_w1t[128 * 128];  // W1^T fp16 (n-major)
__device__ __align__(16) __half g_w2t[64 * 128];   // W2^T fp16 (n-major)
// product-form softmax weights: (exp(v), exp(0.2 v)) pairs
__device__ float2 g_es1[MAXN * 4];
__device__ float2 g_ed1[MAXN * 4];
__device__ float2 g_es2[MAXN];
__device__ float2 g_ed2[MAXN];
__device__ int   g_srcb[MAXE];
__device__ int   g_dstb[MAXE];
__device__ int   g_deg[MAXN];         // zeroed by k_scan after reading (replay-safe)
__device__ int   g_off[MAXN + 1];
__device__ int   g_cur[MAXN];
__device__ int   g_csr[MAXE];
__device__ unsigned long long g_lb[512];

__device__ __forceinline__ bool sniff64(const int* xw) { return xw[1] == 0; }

// 16B-chunk swizzle: row-local XOR keeps ldmatrix column reads conflict-free.
__device__ __forceinline__ int swz(int row, int ch) {
    return (row * 16 + (ch ^ (row & 15))) << 4;   // byte offset
}

__device__ __forceinline__ void ldsm4(unsigned& r0, unsigned& r1,
                                      unsigned& r2, unsigned& r3, unsigned addr) {
    asm volatile("ldmatrix.sync.aligned.m8n8.x4.shared.b16 {%0,%1,%2,%3}, [%4];"
                 : "=r"(r0), "=r"(r1), "=r"(r2), "=r"(r3) : "r"(addr));
}
__device__ __forceinline__ void mma16816(float* c, unsigned a0, unsigned a1,
                                         unsigned a2, unsigned a3,
                                         unsigned b0, unsigned b1) {
    asm volatile(
        "mma.sync.aligned.m16n8k16.row.col.f32.f16.f16.f32 "
        "{%0,%1,%2,%3}, {%4,%5,%6,%7}, {%8,%9}, {%0,%1,%2,%3};"
        : "+f"(c[0]), "+f"(c[1]), "+f"(c[2]), "+f"(c[3])
        : "r"(a0), "r"(a1), "r"(a2), "r"(a3), "r"(b0), "r"(b1));
}
__device__ __forceinline__ void cpa16(unsigned dst, const void* src) {
    asm volatile("cp.async.cg.shared.global [%0], [%1], 16;"
                 :: "r"(dst), "l"(src));
}
__device__ __forceinline__ void cpa_wait() {
    asm volatile("cp.async.commit_group;");
    asm volatile("cp.async.wait_group 0;" ::: "memory");
}
__device__ __forceinline__ float2 exp_pair(float v) {
    return make_float2(__expf(v), __expf(0.2f * v));
}

// ------- merged conversion kernel: 3 block roles -------
__global__ void k_conv(const void* __restrict__ xidx,
                       const float* __restrict__ W1,
                       const float* __restrict__ W2,
                       const float* __restrict__ emb,
                       const void* __restrict__ ei,
                       int n, int e, int nb, int cb) {
    int b = blockIdx.x;
    if (b < nb) {
        int i = b * 256 + threadIdx.x;
        if (i < 512) g_lb[i] = 0ull;
        if (i < 128 * 128) {
            int nn = i >> 7, k = i & 127;
            g_w1t[i] = __float2half(W1[k * 128 + nn]);
        }
        if (i < 64 * 128) {
            int nn = i >> 7, k = i & 127;
            g_w2t[i] = __float2half(W2[k * 64 + nn]);
        }
        return;
    }
    if (b < nb + cb) {
        int node = (b - nb) * 8 + (threadIdx.x >> 5);
        int lane = threadIdx.x & 31;
        if (node >= n) return;
        bool is64 = sniff64((const int*)xidx);
        long long g = is64 ? ((const long long*)xidx)[node]
                           : (long long)((const int*)xidx)[node];
        float4 x = ((const float4*)emb)[g * 32 + lane];
        __half2 h0 = __float22half2_rn(make_float2(x.x, x.y));
        __half2 h1 = __float22half2_rn(make_float2(x.z, x.w));
        g_embh[node * 32 + lane] = make_uint2(*(unsigned*)&h0, *(unsigned*)&h1);
        return;
    }
    int i = (b - nb - cb) * 256 + threadIdx.x;
    if (i >= e) return;
    bool is64 = sniff64((const int*)xidx);
    int s, d;
    if (is64) {
        s = (int)((const long long*)ei)[i];
        d = (int)((const long long*)ei)[(long long)e + i];
    } else {
        s = ((const int*)ei)[i];
        d = ((const int*)ei)[e + i];
    }
    g_srcb[i] = s;
    g_dstb[i] = d;
    atomicAdd(&g_deg[d], 1);
}

// ---------------- single-pass scan, warp-parallel decoupled lookback ----------------
__global__ void k_scan(int n, int etot) {
    __shared__ int s[256];
    __shared__ int s_prefix;
    int tid = threadIdx.x;
    int b = blockIdx.x;
    int i = b * 256 + tid;
    int v = (i < n) ? g_deg[i] : 0;
    s[tid] = v;
    __syncthreads();
    for (int o = 1; o < 256; o <<= 1) {
        int t = 0;
        if (tid >= o) t = s[tid - o];
        __syncthreads();
        s[tid] += t;
        __syncthreads();
    }
    int incl = s[tid];
    int agg = s[255];

    if (tid < 32) {
        if (tid == 0) {
            unsigned long long pub = (b == 0)
                ? ((2ull << 32) | (unsigned)agg)
                : ((1ull << 32) | (unsigned)agg);
            __threadfence();
            atomicExch(&g_lb[b], pub);
        }
        int ex = 0;
        if (b > 0) {
            int p = b - 1;
            while (true) {
                int idx = p - (int)tid;
                unsigned long long st = (idx >= 0) ? atomicAdd(&g_lb[idx], 0ull)
                                                   : (2ull << 32);
                unsigned flag = (unsigned)(st >> 32);
                if (__any_sync(0xffffffffu, flag == 0u)) continue;
                unsigned m2 = __ballot_sync(0xffffffffu, flag == 2u);
                int contrib;
                if (m2) {
                    int L = __ffs(m2) - 1;
                    contrib = ((int)tid <= L) ? (int)(unsigned)st : 0;
                } else {
                    contrib = (int)(unsigned)st;
                }
#pragma unroll
                for (int o = 16; o > 0; o >>= 1)
                    contrib += __shfl_xor_sync(0xffffffffu, contrib, o);
                ex += contrib;
                if (m2) break;
                p -= 32;
            }
            if (tid == 0) {
                __threadfence();
                atomicExch(&g_lb[b], (2ull << 32) | (unsigned)(ex + agg));
            }
        }
        if (tid == 0) s_prefix = ex;
    }
    __syncthreads();
    int ex = s_prefix;
    if (i < n) {
        int o = ex + incl - v;
        g_off[i] = o;
        g_cur[i] = o;
        g_deg[i] = 0;
        if (i == n - 1) g_off[n] = etot;
    }
}

// ---------------- tensor-core GEMM, cp.async staging, fragment-direct epilogue -----
// Block = 64 nodes, 256 threads. Warp = m16 x nCOLS/2 tile. K = 128. A source fp16.
// Epilogues store PRODUCT-FORM softmax factors (exp(v), exp(0.2v)).
template <int LAYER>
__global__ void __launch_bounds__(256, 4) k_gemm(const float* __restrict__ asrc,
                                                 const float* __restrict__ adst,
                                                 int n, int gb, int sb, int e) {
    int gemm_idx = blockIdx.x;
    if (LAYER == 1) {
        int bid = blockIdx.x;
        int mn = (gb < sb) ? gb : sb;
        int both = 2 * mn;
        bool isc;
        int ridx;
        if (bid < both) {
            isc = (bid & 1);
            ridx = bid >> 1;
        } else if (gb >= sb) {
            isc = false;
            ridx = bid - both + mn;
        } else {
            isc = true;
            ridx = bid - both + mn;
        }
        if (isc) {
            int start = ridx * 1024 + threadIdx.x;
#pragma unroll
            for (int k = 0; k < 4; k++) {
                int i = start + k * 256;
                if (i < e) {
                    int pos = atomicAdd(&g_cur[g_dstb[i]], 1);
                    g_csr[pos] = g_srcb[i];
                }
            }
            return;
        }
        gemm_idx = ridx;
    }

    constexpr int COLS = (LAYER == 1) ? 128 : 64;
    constexpr int NT2 = COLS / 16;          // n-tiles per warp: 8 / 4
    constexpr int SBYTES = 16384 + COLS * 256;

    __shared__ __align__(16) char sbuf[SBYTES];
    char* Ab = sbuf;
    char* Bb = sbuf + 16384;

    const int tid = threadIdx.x;
    const int lane = tid & 31;
    const int wid = tid >> 5;
    const int base = gemm_idx * 64;

    unsigned a_u = (unsigned)__cvta_generic_to_shared(Ab);
    unsigned b_u = (unsigned)__cvta_generic_to_shared(Bb);

    // ---- stage A (fp16 node rows, cp.async) ----
    const uint2* Asrc = (LAYER == 1) ? g_embh : g_x2h;
#pragma unroll 4
    for (int idx = tid; idx < 64 * 16; idx += 256) {
        int r = idx >> 4, ch = idx & 15;
        int node = base + r;
        if (node < n) cpa16(a_u + swz(r, ch), Asrc + node * 32 + ch * 2);
        else *(uint4*)(Ab + swz(r, ch)) = make_uint4(0, 0, 0, 0);
    }
    // ---- stage B = W^T (cp.async) ----
    {
        const uint4* Wt = (const uint4*)((LAYER == 1) ? g_w1t : g_w2t);
#pragma unroll 4
        for (int idx = tid; idx < COLS * 16; idx += 256) {
            int r = idx >> 4, ch = idx & 15;
            cpa16(b_u + swz(r, ch), Wt + r * 16 + ch);
        }
    }
    cpa_wait();
    __syncthreads();

    // ---- mma mainloop: warp = m16 (mw) x n-half (nh) ----
    const int mw = wid >> 1;
    const int nh = wid & 1;
    const int m0 = mw * 16;

    float c[NT2][4];
#pragma unroll
    for (int j = 0; j < NT2; j++)
#pragma unroll
        for (int q = 0; q < 4; q++) c[j][q] = 0.f;

    const int tl = lane >> 3;
    const int rr = lane & 7;

#pragma unroll
    for (int s = 0; s < 8; s++) {
        int chunk = 2 * s + (tl >> 1);
        unsigned a0, a1, a2, a3;
        ldsm4(a0, a1, a2, a3, a_u + swz(m0 + (tl & 1) * 8 + rr, chunk));
#pragma unroll
        for (int t = 0; t < NT2 / 2; t++) {
            int brow = nh * (NT2 * 8) + t * 16;
            unsigned r0, r1, r2, r3;
            ldsm4(r0, r1, r2, r3, b_u + swz(brow + (tl & 1) * 8 + rr, chunk));
            mma16816(c[2 * t], a0, a1, a2, a3, r0, r2);
            mma16816(c[2 * t + 1], a0, a1, a2, a3, r1, r3);
        }
    }

    // ---- fragment-direct epilogue ----
    const int g = lane >> 2;
    const int tg = lane & 3;
    const int colbase = nh * (NT2 * 8);     // 0/64 (L1), 0/32 (L2)
    const int node0 = base + m0 + g;
    const int node1 = node0 + 8;

    if (LAYER == 1) {
        // warp half covers 2 complete heads (cols colbase..colbase+63)
        float s0a = 0.f, s0b = 0.f, d0a = 0.f, d0b = 0.f;   // row g
        float s1a = 0.f, s1b = 0.f, d1a = 0.f, d1b = 0.f;   // row g+8
#pragma unroll
        for (int j = 0; j < 8; j++) {
            int col = colbase + j * 8 + 2 * tg;
            float2 as = __ldg((const float2*)(asrc + col));
            float2 ad = __ldg((const float2*)(adst + col));
            float ps0 = c[j][0] * as.x + c[j][1] * as.y;
            float pd0 = c[j][0] * ad.x + c[j][1] * ad.y;
            float ps1 = c[j][2] * as.x + c[j][3] * as.y;
            float pd1 = c[j][2] * ad.x + c[j][3] * ad.y;
            if (j < 4) { s0a += ps0; d0a += pd0; s1a += ps1; d1a += pd1; }
            else       { s0b += ps0; d0b += pd0; s1b += ps1; d1b += pd1; }
        }
#pragma unroll
        for (int o = 1; o < 4; o <<= 1) {
            s0a += __shfl_xor_sync(0xffffffffu, s0a, o);
            s0b += __shfl_xor_sync(0xffffffffu, s0b, o);
            d0a += __shfl_xor_sync(0xffffffffu, d0a, o);
            d0b += __shfl_xor_sync(0xffffffffu, d0b, o);
            s1a += __shfl_xor_sync(0xffffffffu, s1a, o);
            s1b += __shfl_xor_sync(0xffffffffu, s1b, o);
            d1a += __shfl_xor_sync(0xffffffffu, d1a, o);
            d1b += __shfl_xor_sync(0xffffffffu, d1b, o);
        }
        int h0i = 2 * nh, h1i = 2 * nh + 1;
        if (tg == 0) {
            if (node0 < n) {
                g_es1[node0 * 4 + h0i] = exp_pair(s0a);
                g_es1[node0 * 4 + h1i] = exp_pair(s0b);
                g_ed1[node0 * 4 + h0i] = exp_pair(d0a);
                g_ed1[node0 * 4 + h1i] = exp_pair(d0b);
            }
            if (node1 < n) {
                g_es1[node1 * 4 + h0i] = exp_pair(s1a);
                g_es1[node1 * 4 + h1i] = exp_pair(s1b);
                g_ed1[node1 * 4 + h0i] = exp_pair(d1a);
                g_ed1[node1 * 4 + h1i] = exp_pair(d1b);
            }
        }
        unsigned* H = (unsigned*)g_h1h;     // node*64 unsigneds (half2 each)
#pragma unroll
        for (int j = 0; j < 8; j++) {
            int ci = (colbase >> 1) + j * 4 + tg;
            __half2 h0 = __float22half2_rn(make_float2(c[j][0], c[j][1]));
            __half2 h1 = __float22half2_rn(make_float2(c[j][2], c[j][3]));
            if (node0 < n) H[node0 * 64 + ci] = *(unsigned*)&h0;
            if (node1 < n) H[node1 * 64 + ci] = *(unsigned*)&h1;
        }
    } else {
        // single head spans both warp halves: combine partials in smem, then exp
        float s0 = 0.f, d0 = 0.f, s1 = 0.f, d1 = 0.f;
#pragma unroll
        for (int j = 0; j < 4; j++) {
            int col = colbase + j * 8 + 2 * tg;
            float2 as = __ldg((const float2*)(asrc + col));
            float2 ad = __ldg((const float2*)(adst + col));
            s0 += c[j][0] * as.x + c[j][1] * as.y;
            d0 += c[j][0] * ad.x + c[j][1] * ad.y;
            s1 += c[j][2] * as.x + c[j][3] * as.y;
            d1 += c[j][2] * ad.x + c[j][3] * ad.y;
        }
#pragma unroll
        for (int o = 1; o < 4; o <<= 1) {
            s0 += __shfl_xor_sync(0xffffffffu, s0, o);
            d0 += __shfl_xor_sync(0xffffffffu, d0, o);
            s1 += __shfl_xor_sync(0xffffffffu, s1, o);
            d1 += __shfl_xor_sync(0xffffffffu, d1, o);
        }
        // feature stores (independent of combine)
        unsigned* H = (unsigned*)g_h2h;     // node*32 unsigneds
#pragma unroll
        for (int j = 0; j < 4; j++) {
            int ci = (colbase >> 1) + j * 4 + tg;
            __half2 h0 = __float22half2_rn(make_float2(c[j][0], c[j][1]));
            __half2 h1 = __float22half2_rn(make_float2(c[j][2], c[j][3]));
            if (node0 < n) H[node0 * 32 + ci] = *(unsigned*)&h0;
            if (node1 < n) H[node1 * 32 + ci] = *(unsigned*)&h1;
        }
        // combine the two warp-half partials via smem (overlay on staging buffer)
        __syncthreads();                      // all ldsm reads of Ab/Bb done
        float* sC = (float*)sbuf;             // [64][4]: s_nh0, s_nh1, d_nh0, d_nh1
        if (tg == 0) {
            int r0 = m0 + g, r1 = m0 + g + 8;
            sC[r0 * 4 + nh] = s0;
            sC[r0 * 4 + 2 + nh] = d0;
            sC[r1 * 4 + nh] = s1;
            sC[r1 * 4 + 2 + nh] = d1;
        }
        __syncthreads();
        if (tid < 64) {
            int node = base + tid;
            if (node < n) {
                float s = sC[tid * 4] + sC[tid * 4 + 1];
                float d = sC[tid * 4 + 2] + sC[tid * 4 + 3];
                g_es2[node] = exp_pair(s);
                g_ed2[node] = exp_pair(d);
            }
        }
    }
}

// ---------------- fused gather layer 1: product-form weights, no MUFU in loop -------
__global__ void k_gather1(const float* __restrict__ b1, int n) {
    int node = (blockIdx.x * blockDim.x + threadIdx.x) >> 5;
    int lane = threadIdx.x & 31;
    if (node >= n) return;
    int head = lane >> 3;

    float2 ed = g_ed1[node * 4 + head];

    // self loop
    float2 e0 = g_es1[node * 4 + head];
    float p = e0.x * ed.x, q = e0.y * ed.y;
    float w = (p > 1.f) ? p : q;
    uint2 pk = g_h1h[node * 32 + lane];
    float2 f0 = __half22float2(*(const __half2*)&pk.x);
    float2 f1 = __half22float2(*(const __half2*)&pk.y);
    float4 acc = make_float4(w * f0.x, w * f0.y, w * f1.x, w * f1.y);
    float wsum = w;

    int i = g_off[node];
    int iend = g_off[node + 1];
    for (; i < iend; i++) {
        int src = g_csr[i];
        float2 es = g_es1[src * 4 + head];
        float pp = es.x * ed.x, qq = es.y * ed.y;
        float ww = (pp > 1.f) ? pp : qq;
        uint2 qk = g_h1h[src * 32 + lane];
        float2 v0 = __half22float2(*(const __half2*)&qk.x);
        float2 v1 = __half22float2(*(const __half2*)&qk.y);
        acc.x += ww * v0.x;
        acc.y += ww * v0.y;
        acc.z += ww * v1.x;
        acc.w += ww * v1.y;
        wsum += ww;
    }
    float inv = 1.f / wsum;
    float4 bb = ((const float4*)b1)[lane];
    float ox = acc.x * inv + bb.x;
    float oy = acc.y * inv + bb.y;
    float oz = acc.z * inv + bb.z;
    float ow = acc.w * inv + bb.w;
    ox = (ox > 0.f) ? ox : expm1f(ox);
    oy = (oy > 0.f) ? oy : expm1f(oy);
    oz = (oz > 0.f) ? oz : expm1f(oz);
    ow = (ow > 0.f) ? ow : expm1f(ow);
    __half2 h0 = __float22half2_rn(make_float2(ox, oy));
    __half2 h1 = __float22half2_rn(make_float2(oz, ow));
    g_x2h[node * 32 + lane] = make_uint2(*(unsigned*)&h0, *(unsigned*)&h1);
}

// ---------------- fused gather layer 2: product-form weights ----------------
__global__ void k_gather2(const float* __restrict__ b2, float* __restrict__ out, int n) {
    int node = (blockIdx.x * blockDim.x + threadIdx.x) >> 5;
    int lane = threadIdx.x & 31;
    if (node >= n) return;

    const __half2* H2 = (const __half2*)g_h2h;
    float2 ed = g_ed2[node];

    float2 e0 = g_es2[node];
    float p = e0.x * ed.x, q = e0.y * ed.y;
    float w = (p > 1.f) ? p : q;
    float2 hv = __half22float2(H2[node * 32 + lane]);
    float2 acc = make_float2(w * hv.x, w * hv.y);
    float wsum = w;

    int i = g_off[node];
    int iend = g_off[node + 1];
    for (; i < iend; i++) {
        int src = g_csr[i];
        float2 es = g_es2[src];
        float pp = es.x * ed.x, qq = es.y * ed.y;
        float ww = (pp > 1.f) ? pp : qq;
        float2 v = __half22float2(H2[src * 32 + lane]);
        acc.x += ww * v.x;
        acc.y += ww * v.y;
        wsum += ww;
    }
    float inv = 1.f / wsum;
    float2 bb = ((const float2*)b2)[lane];
    ((float2*)out)[node * 32 + lane] =
        make_float2(acc.x * inv + bb.x, acc.y * inv + bb.y);
}

// ---------------- launch ----------------
extern "C" void kernel_launch(void* const* d_in, const int* in_sizes, int n_in,
                              void* d_out, int out_size) {
    const void* xidx = d_in[0];
    const void* ei = d_in[1];
    const float* emb = (const float*)d_in[2];
    const float* W1 = (const float*)d_in[3];
    const float* a_src1 = (const float*)d_in[4];
    const float* a_dst1 = (const float*)d_in[5];
    const float* b1 = (const float*)d_in[6];
    const float* W2 = (const float*)d_in[7];
    const float* a_src2 = (const float*)d_in[8];
    const float* a_dst2 = (const float*)d_in[9];
    const float* b2 = (const float*)d_in[10];
    float* out = (float*)d_out;

    int n = in_sizes[0];
    int e = in_sizes[1] / 2;

    int nb256 = (n + 255) / 256;
    int eb256 = (e + 255) / 256;
    int nwarp = (n + 7) / 8;
    int gb = (n + 63) / 64;
    int sb = (e + 1023) / 1024;   // scatter blocks: 256 thr x 4 edges
    int cb = (n + 7) / 8;         // emb-convert blocks: 8 warps/block, warp/node

    k_conv<<<nb256 + cb + eb256, 256>>>(xidx, W1, W2, emb, ei, n, e, nb256, cb);
    k_scan<<<nb256, 256>>>(n, e);

    k_gemm<1><<<gb + sb, 256>>>(a_src1, a_dst1, n, gb, sb, e);
    k_gather1<<<nwarp, 256>>>(b1, n);

    k_gemm<2><<<gb, 256>>>(a_src2, a_dst2, n, gb, 0, 0);
    k_gather2<<<nwarp, 256>>>(b2, out, n);
}

// round 15
// speedup vs baseline: 1.1684x; 1.1225x over previous
#include <cuda_runtime.h>
#include <cuda_bf16.h>
#include <cuda_fp16.h>
#include <math.h>

#define MAXN 100000
#define MAXE 1600000

// ---------------- device scratch ----------------
__device__ __align__(16) uint2 g_embh[MAXN * 32];  // gathered emb rows, fp16
__device__ __align__(16) uint4 g_h1h[MAXN * 16];   // layer1 features (128 halves/node)
__device__ __align__(16) uint4 g_x2h[MAXN * 16];   // layer1 output fp16 (128/node)
__device__ __align__(16) uint4 g_h2h[MAXN * 8];    // layer2 features (64 halves/node)
__device__ __align__(16) __half g_w1t[128 * 128];  // W1^T fp16 (n-major)
__device__ __align__(16) __half g_w2t[64 * 128];   // W2^T fp16 (n-major)
// product-form softmax weights: (exp(v), exp(0.2 v)) pairs
__device__ float2 g_es1[MAXN * 4];
__device__ float2 g_ed1[MAXN * 4];
__device__ float2 g_es2[MAXN];
__device__ float2 g_ed2[MAXN];
__device__ int   g_srcb[MAXE];
__device__ int   g_dstb[MAXE];
__device__ int   g_deg[MAXN];         // zeroed by k_scan after reading (replay-safe)
__device__ int   g_off[MAXN + 1];
__device__ int   g_cur[MAXN];
__device__ int   g_csr[MAXE];
__device__ unsigned long long g_lb[512];

__device__ __forceinline__ bool sniff64(const int* xw) { return xw[1] == 0; }

// 16B-chunk swizzle: row-local XOR keeps ldmatrix column reads conflict-free.
__device__ __forceinline__ int swz(int row, int ch) {
    return (row * 16 + (ch ^ (row & 15))) << 4;   // byte offset
}

__device__ __forceinline__ void ldsm4(unsigned& r0, unsigned& r1,
                                      unsigned& r2, unsigned& r3, unsigned addr) {
    asm volatile("ldmatrix.sync.aligned.m8n8.x4.shared.b16 {%0,%1,%2,%3}, [%4];"
                 : "=r"(r0), "=r"(r1), "=r"(r2), "=r"(r3) : "r"(addr));
}
__device__ __forceinline__ void mma16816(float* c, unsigned a0, unsigned a1,
                                         unsigned a2, unsigned a3,
                                         unsigned b0, unsigned b1) {
    asm volatile(
        "mma.sync.aligned.m16n8k16.row.col.f32.f16.f16.f32 "
        "{%0,%1,%2,%3}, {%4,%5,%6,%7}, {%8,%9}, {%0,%1,%2,%3};"
        : "+f"(c[0]), "+f"(c[1]), "+f"(c[2]), "+f"(c[3])
        : "r"(a0), "r"(a1), "r"(a2), "r"(a3), "r"(b0), "r"(b1));
}
__device__ __forceinline__ void cpa16(unsigned dst, const void* src) {
    asm volatile("cp.async.cg.shared.global [%0], [%1], 16;"
                 :: "r"(dst), "l"(src));
}
__device__ __forceinline__ void cpa_wait() {
    asm volatile("cp.async.commit_group;");
    asm volatile("cp.async.wait_group 0;" ::: "memory");
}
__device__ __forceinline__ float2 exp_pair(float v) {
    return make_float2(__expf(v), __expf(0.2f * v));
}

// ------- merged conversion kernel: 3 block roles -------
__global__ void k_conv(const void* __restrict__ xidx,
                       const float* __restrict__ W1,
                       const float* __restrict__ W2,
                       const float* __restrict__ emb,
                       const void* __restrict__ ei,
                       int n, int e, int nb, int cb) {
    int b = blockIdx.x;
    if (b < nb) {
        int i = b * 256 + threadIdx.x;
        if (i < 512) g_lb[i] = 0ull;
        if (i < 128 * 128) {
            int nn = i >> 7, k = i & 127;
            g_w1t[i] = __float2half(W1[k * 128 + nn]);
        }
        if (i < 64 * 128) {
            int nn = i >> 7, k = i & 127;
            g_w2t[i] = __float2half(W2[k * 64 + nn]);
        }
        return;
    }
    if (b < nb + cb) {
        int node = (b - nb) * 8 + (threadIdx.x >> 5);
        int lane = threadIdx.x & 31;
        if (node >= n) return;
        bool is64 = sniff64((const int*)xidx);
        long long g = is64 ? ((const long long*)xidx)[node]
                           : (long long)((const int*)xidx)[node];
        float4 x = ((const float4*)emb)[g * 32 + lane];
        __half2 h0 = __float22half2_rn(make_float2(x.x, x.y));
        __half2 h1 = __float22half2_rn(make_float2(x.z, x.w));
        g_embh[node * 32 + lane] = make_uint2(*(unsigned*)&h0, *(unsigned*)&h1);
        return;
    }
    int i = (b - nb - cb) * 256 + threadIdx.x;
    if (i >= e) return;
    bool is64 = sniff64((const int*)xidx);
    int s, d;
    if (is64) {
        s = (int)((const long long*)ei)[i];
        d = (int)((const long long*)ei)[(long long)e + i];
    } else {
        s = ((const int*)ei)[i];
        d = ((const int*)ei)[e + i];
    }
    g_srcb[i] = s;
    g_dstb[i] = d;
    atomicAdd(&g_deg[d], 1);
}

// ---------------- single-pass scan, warp-parallel decoupled lookback ----------------
__global__ void k_scan(int n, int etot) {
    __shared__ int s[256];
    __shared__ int s_prefix;
    int tid = threadIdx.x;
    int b = blockIdx.x;
    int i = b * 256 + tid;
    int v = (i < n) ? g_deg[i] : 0;
    s[tid] = v;
    __syncthreads();
    for (int o = 1; o < 256; o <<= 1) {
        int t = 0;
        if (tid >= o) t = s[tid - o];
        __syncthreads();
        s[tid] += t;
        __syncthreads();
    }
    int incl = s[tid];
    int agg = s[255];

    if (tid < 32) {
        if (tid == 0) {
            unsigned long long pub = (b == 0)
                ? ((2ull << 32) | (unsigned)agg)
                : ((1ull << 32) | (unsigned)agg);
            __threadfence();
            atomicExch(&g_lb[b], pub);
        }
        int ex = 0;
        if (b > 0) {
            int p = b - 1;
            while (true) {
                int idx = p - (int)tid;
                unsigned long long st = (idx >= 0) ? atomicAdd(&g_lb[idx], 0ull)
                                                   : (2ull << 32);
                unsigned flag = (unsigned)(st >> 32);
                if (__any_sync(0xffffffffu, flag == 0u)) continue;
                unsigned m2 = __ballot_sync(0xffffffffu, flag == 2u);
                int contrib;
                if (m2) {
                    int L = __ffs(m2) - 1;
                    contrib = ((int)tid <= L) ? (int)(unsigned)st : 0;
                } else {
                    contrib = (int)(unsigned)st;
                }
#pragma unroll
                for (int o = 16; o > 0; o >>= 1)
                    contrib += __shfl_xor_sync(0xffffffffu, contrib, o);
                ex += contrib;
                if (m2) break;
                p -= 32;
            }
            if (tid == 0) {
                __threadfence();
                atomicExch(&g_lb[b], (2ull << 32) | (unsigned)(ex + agg));
            }
        }
        if (tid == 0) s_prefix = ex;
    }
    __syncthreads();
    int ex = s_prefix;
    if (i < n) {
        int o = ex + incl - v;
        g_off[i] = o;
        g_cur[i] = o;
        g_deg[i] = 0;
        if (i == n - 1) g_off[n] = etot;
    }
}

// ---------------- tensor-core GEMM, cp.async staging, fragment-direct epilogue -----
template <int LAYER>
__global__ void __launch_bounds__(256, 4) k_gemm(const float* __restrict__ asrc,
                                                 const float* __restrict__ adst,
                                                 int n, int gb, int sb, int e) {
    int gemm_idx = blockIdx.x;
    if (LAYER == 1) {
        int bid = blockIdx.x;
        int mn = (gb < sb) ? gb : sb;
        int both = 2 * mn;
        bool isc;
        int ridx;
        if (bid < both) {
            isc = (bid & 1);
            ridx = bid >> 1;
        } else if (gb >= sb) {
            isc = false;
            ridx = bid - both + mn;
        } else {
            isc = true;
            ridx = bid - both + mn;
        }
        if (isc) {
            int start = ridx * 1024 + threadIdx.x;
#pragma unroll
            for (int k = 0; k < 4; k++) {
                int i = start + k * 256;
                if (i < e) {
                    int pos = atomicAdd(&g_cur[g_dstb[i]], 1);
                    g_csr[pos] = g_srcb[i];
                }
            }
            return;
        }
        gemm_idx = ridx;
    }

    constexpr int COLS = (LAYER == 1) ? 128 : 64;
    constexpr int NT2 = COLS / 16;          // n-tiles per warp: 8 / 4
    constexpr int SBYTES = 16384 + COLS * 256;

    __shared__ __align__(16) char sbuf[SBYTES];
    char* Ab = sbuf;
    char* Bb = sbuf + 16384;

    const int tid = threadIdx.x;
    const int lane = tid & 31;
    const int wid = tid >> 5;
    const int base = gemm_idx * 64;

    unsigned a_u = (unsigned)__cvta_generic_to_shared(Ab);
    unsigned b_u = (unsigned)__cvta_generic_to_shared(Bb);

    // ---- stage A (fp16 node rows, cp.async) ----
    const uint4* Asrc = (LAYER == 1) ? (const uint4*)g_embh : g_x2h;
#pragma unroll 4
    for (int idx = tid; idx < 64 * 16; idx += 256) {
        int r = idx >> 4, ch = idx & 15;
        int node = base + r;
        if (node < n) cpa16(a_u + swz(r, ch), Asrc + node * 16 + ch);
        else *(uint4*)(Ab + swz(r, ch)) = make_uint4(0, 0, 0, 0);
    }
    // ---- stage B = W^T (cp.async) ----
    {
        const uint4* Wt = (const uint4*)((LAYER == 1) ? g_w1t : g_w2t);
#pragma unroll 4
        for (int idx = tid; idx < COLS * 16; idx += 256) {
            int r = idx >> 4, ch = idx & 15;
            cpa16(b_u + swz(r, ch), Wt + r * 16 + ch);
        }
    }
    cpa_wait();
    __syncthreads();

    // ---- mma mainloop: warp = m16 (mw) x n-half (nh) ----
    const int mw = wid >> 1;
    const int nh = wid & 1;
    const int m0 = mw * 16;

    float c[NT2][4];
#pragma unroll
    for (int j = 0; j < NT2; j++)
#pragma unroll
        for (int q = 0; q < 4; q++) c[j][q] = 0.f;

    const int tl = lane >> 3;
    const int rr = lane & 7;

#pragma unroll
    for (int s = 0; s < 8; s++) {
        int chunk = 2 * s + (tl >> 1);
        unsigned a0, a1, a2, a3;
        ldsm4(a0, a1, a2, a3, a_u + swz(m0 + (tl & 1) * 8 + rr, chunk));
#pragma unroll
        for (int t = 0; t < NT2 / 2; t++) {
            int brow = nh * (NT2 * 8) + t * 16;
            unsigned r0, r1, r2, r3;
            ldsm4(r0, r1, r2, r3, b_u + swz(brow + (tl & 1) * 8 + rr, chunk));
            mma16816(c[2 * t], a0, a1, a2, a3, r0, r2);
            mma16816(c[2 * t + 1], a0, a1, a2, a3, r1, r3);
        }
    }

    // ---- fragment-direct epilogue ----
    const int g = lane >> 2;
    const int tg = lane & 3;
    const int colbase = nh * (NT2 * 8);     // 0/64 (L1), 0/32 (L2)
    const int node0 = base + m0 + g;
    const int node1 = node0 + 8;

    if (LAYER == 1) {
        float s0a = 0.f, s0b = 0.f, d0a = 0.f, d0b = 0.f;   // row g
        float s1a = 0.f, s1b = 0.f, d1a = 0.f, d1b = 0.f;   // row g+8
#pragma unroll
        for (int j = 0; j < 8; j++) {
            int col = colbase + j * 8 + 2 * tg;
            float2 as = __ldg((const float2*)(asrc + col));
            float2 ad = __ldg((const float2*)(adst + col));
            float ps0 = c[j][0] * as.x + c[j][1] * as.y;
            float pd0 = c[j][0] * ad.x + c[j][1] * ad.y;
            float ps1 = c[j][2] * as.x + c[j][3] * as.y;
            float pd1 = c[j][2] * ad.x + c[j][3] * ad.y;
            if (j < 4) { s0a += ps0; d0a += pd0; s1a += ps1; d1a += pd1; }
            else       { s0b += ps0; d0b += pd0; s1b += ps1; d1b += pd1; }
        }
#pragma unroll
        for (int o = 1; o < 4; o <<= 1) {
            s0a += __shfl_xor_sync(0xffffffffu, s0a, o);
            s0b += __shfl_xor_sync(0xffffffffu, s0b, o);
            d0a += __shfl_xor_sync(0xffffffffu, d0a, o);
            d0b += __shfl_xor_sync(0xffffffffu, d0b, o);
            s1a += __shfl_xor_sync(0xffffffffu, s1a, o);
            s1b += __shfl_xor_sync(0xffffffffu, s1b, o);
            d1a += __shfl_xor_sync(0xffffffffu, d1a, o);
            d1b += __shfl_xor_sync(0xffffffffu, d1b, o);
        }
        int h0i = 2 * nh, h1i = 2 * nh + 1;
        if (tg == 0) {
            if (node0 < n) {
                g_es1[node0 * 4 + h0i] = exp_pair(s0a);
                g_es1[node0 * 4 + h1i] = exp_pair(s0b);
                g_ed1[node0 * 4 + h0i] = exp_pair(d0a);
                g_ed1[node0 * 4 + h1i] = exp_pair(d0b);
            }
            if (node1 < n) {
                g_es1[node1 * 4 + h0i] = exp_pair(s1a);
                g_es1[node1 * 4 + h1i] = exp_pair(s1b);
                g_ed1[node1 * 4 + h0i] = exp_pair(d1a);
                g_ed1[node1 * 4 + h1i] = exp_pair(d1b);
            }
        }
        unsigned* H = (unsigned*)g_h1h;     // node*64 unsigneds (half2 each)
#pragma unroll
        for (int j = 0; j < 8; j++) {
            int ci = (colbase >> 1) + j * 4 + tg;
            __half2 h0 = __float22half2_rn(make_float2(c[j][0], c[j][1]));
            __half2 h1 = __float22half2_rn(make_float2(c[j][2], c[j][3]));
            if (node0 < n) H[node0 * 64 + ci] = *(unsigned*)&h0;
            if (node1 < n) H[node1 * 64 + ci] = *(unsigned*)&h1;
        }
    } else {
        float s0 = 0.f, d0 = 0.f, s1 = 0.f, d1 = 0.f;
#pragma unroll
        for (int j = 0; j < 4; j++) {
            int col = colbase + j * 8 + 2 * tg;
            float2 as = __ldg((const float2*)(asrc + col));
            float2 ad = __ldg((const float2*)(adst + col));
            s0 += c[j][0] * as.x + c[j][1] * as.y;
            d0 += c[j][0] * ad.x + c[j][1] * ad.y;
            s1 += c[j][2] * as.x + c[j][3] * as.y;
            d1 += c[j][2] * ad.x + c[j][3] * ad.y;
        }
#pragma unroll
        for (int o = 1; o < 4; o <<= 1) {
            s0 += __shfl_xor_sync(0xffffffffu, s0, o);
            d0 += __shfl_xor_sync(0xffffffffu, d0, o);
            s1 += __shfl_xor_sync(0xffffffffu, s1, o);
            d1 += __shfl_xor_sync(0xffffffffu, d1, o);
        }
        unsigned* H = (unsigned*)g_h2h;     // node*32 unsigneds
#pragma unroll
        for (int j = 0; j < 4; j++) {
            int ci = (colbase >> 1) + j * 4 + tg;
            __half2 h0 = __float22half2_rn(make_float2(c[j][0], c[j][1]));
            __half2 h1 = __float22half2_rn(make_float2(c[j][2], c[j][3]));
            if (node0 < n) H[node0 * 32 + ci] = *(unsigned*)&h0;
            if (node1 < n) H[node1 * 32 + ci] = *(unsigned*)&h1;
        }
        // combine the two warp-half partials via smem (overlay on staging buffer)
        __syncthreads();
        float* sC = (float*)sbuf;             // [64][4]
        if (tg == 0) {
            int r0 = m0 + g, r1 = m0 + g + 8;
            sC[r0 * 4 + nh] = s0;
            sC[r0 * 4 + 2 + nh] = d0;
            sC[r1 * 4 + nh] = s1;
            sC[r1 * 4 + 2 + nh] = d1;
        }
        __syncthreads();
        if (tid < 64) {
            int node = base + tid;
            if (node < n) {
                float s = sC[tid * 4] + sC[tid * 4 + 1];
                float d = sC[tid * 4 + 2] + sC[tid * 4 + 3];
                g_es2[node] = exp_pair(s);
                g_ed2[node] = exp_pair(d);
            }
        }
    }
}

// ---- fused gather layer 1: 2 nodes/warp (16 lanes each, 8 cols/lane) ----
__global__ void k_gather1(const float* __restrict__ b1, int n) {
    int warp = (blockIdx.x * blockDim.x + threadIdx.x) >> 5;
    int lane = threadIdx.x & 31;
    int sl = lane & 15;                    // sublane within node
    int node = warp * 2 + (lane >> 4);
    if (node >= n) return;
    int head = sl >> 2;                    // 4 lanes per head

    float2 ed = g_ed1[node * 4 + head];

    // self loop
    float2 e0 = g_es1[node * 4 + head];
    float p = e0.x * ed.x, q = e0.y * ed.y;
    float w = (p > 1.f) ? p : q;
    uint4 pk = g_h1h[node * 16 + sl];
    float2 f0 = __half22float2(*(const __half2*)&pk.x);
    float2 f1 = __half22float2(*(const __half2*)&pk.y);
    float2 f2 = __half22float2(*(const __half2*)&pk.z);
    float2 f3 = __half22float2(*(const __half2*)&pk.w);
    float a0 = w * f0.x, a1 = w * f0.y, a2 = w * f1.x, a3 = w * f1.y;
    float a4 = w * f2.x, a5 = w * f2.y, a6 = w * f3.x, a7 = w * f3.y;
    float wsum = w;

    int i = g_off[node];
    int iend = g_off[node + 1];
    for (; i < iend; i++) {
        int src = g_csr[i];
        float2 es = g_es1[src * 4 + head];
        float pp = es.x * ed.x, qq = es.y * ed.y;
        float ww = (pp > 1.f) ? pp : qq;
        uint4 qk = g_h1h[src * 16 + sl];
        float2 v0 = __half22float2(*(const __half2*)&qk.x);
        float2 v1 = __half22float2(*(const __half2*)&qk.y);
        float2 v2 = __half22float2(*(const __half2*)&qk.z);
        float2 v3 = __half22float2(*(const __half2*)&qk.w);
        a0 += ww * v0.x; a1 += ww * v0.y;
        a2 += ww * v1.x; a3 += ww * v1.y;
        a4 += ww * v2.x; a5 += ww * v2.y;
        a6 += ww * v3.x; a7 += ww * v3.y;
        wsum += ww;
    }
    float inv = 1.f / wsum;
    float4 bb0 = ((const float4*)b1)[sl * 2];
    float4 bb1 = ((const float4*)b1)[sl * 2 + 1];
    float o0 = a0 * inv + bb0.x, o1 = a1 * inv + bb0.y;
    float o2 = a2 * inv + bb0.z, o3 = a3 * inv + bb0.w;
    float o4 = a4 * inv + bb1.x, o5 = a5 * inv + bb1.y;
    float o6 = a6 * inv + bb1.z, o7 = a7 * inv + bb1.w;
    o0 = (o0 > 0.f) ? o0 : expm1f(o0);
    o1 = (o1 > 0.f) ? o1 : expm1f(o1);
    o2 = (o2 > 0.f) ? o2 : expm1f(o2);
    o3 = (o3 > 0.f) ? o3 : expm1f(o3);
    o4 = (o4 > 0.f) ? o4 : expm1f(o4);
    o5 = (o5 > 0.f) ? o5 : expm1f(o5);
    o6 = (o6 > 0.f) ? o6 : expm1f(o6);
    o7 = (o7 > 0.f) ? o7 : expm1f(o7);
    __half2 h0 = __float22half2_rn(make_float2(o0, o1));
    __half2 h1 = __float22half2_rn(make_float2(o2, o3));
    __half2 h2 = __float22half2_rn(make_float2(o4, o5));
    __half2 h3 = __float22half2_rn(make_float2(o6, o7));
    g_x2h[node * 16 + sl] = make_uint4(*(unsigned*)&h0, *(unsigned*)&h1,
                                       *(unsigned*)&h2, *(unsigned*)&h3);
}

// ---- fused gather layer 2: 4 nodes/warp (8 lanes each, 8 cols/lane) ----
__global__ void k_gather2(const float* __restrict__ b2, float* __restrict__ out, int n) {
    int warp = (blockIdx.x * blockDim.x + threadIdx.x) >> 5;
    int lane = threadIdx.x & 31;
    int sl = lane & 7;                     // sublane within node
    int node = warp * 4 + (lane >> 3);
    if (node >= n) return;

    float2 ed = g_ed2[node];

    float2 e0 = g_es2[node];
    float p = e0.x * ed.x, q = e0.y * ed.y;
    float w = (p > 1.f) ? p : q;
    uint4 pk = g_h2h[node * 8 + sl];
    float2 f0 = __half22float2(*(const __half2*)&pk.x);
    float2 f1 = __half22float2(*(const __half2*)&pk.y);
    float2 f2 = __half22float2(*(const __half2*)&pk.z);
    float2 f3 = __half22float2(*(const __half2*)&pk.w);
    float a0 = w * f0.x, a1 = w * f0.y, a2 = w * f1.x, a3 = w * f1.y;
    float a4 = w * f2.x, a5 = w * f2.y, a6 = w * f3.x, a7 = w * f3.y;
    float wsum = w;

    int i = g_off[node];
    int iend = g_off[node + 1];
    for (; i < iend; i++) {
        int src = g_csr[i];
        float2 es = g_es2[src];
        float pp = es.x * ed.x, qq = es.y * ed.y;
        float ww = (pp > 1.f) ? pp : qq;
        uint4 qk = g_h2h[src * 8 + sl];
        float2 v0 = __half22float2(*(const __half2*)&qk.x);
        float2 v1 = __half22float2(*(const __half2*)&qk.y);
        float2 v2 = __half22float2(*(const __half2*)&qk.z);
        float2 v3 = __half22float2(*(const __half2*)&qk.w);
        a0 += ww * v0.x; a1 += ww * v0.y;
        a2 += ww * v1.x; a3 += ww * v1.y;
        a4 += ww * v2.x; a5 += ww * v2.y;
        a6 += ww * v3.x; a7 += ww * v3.y;
        wsum += ww;
    }
    float inv = 1.f / wsum;
    float4 bb0 = ((const float4*)b2)[sl * 2];
    float4 bb1 = ((const float4*)b2)[sl * 2 + 1];
    float4 r0 = make_float4(a0 * inv + bb0.x, a1 * inv + bb0.y,
                            a2 * inv + bb0.z, a3 * inv + bb0.w);
    float4 r1 = make_float4(a4 * inv + bb1.x, a5 * inv + bb1.y,
                            a6 * inv + bb1.z, a7 * inv + bb1.w);
    ((float4*)out)[node * 16 + sl * 2] = r0;
    ((float4*)out)[node * 16 + sl * 2 + 1] = r1;
}

// ---------------- launch ----------------
extern "C" void kernel_launch(void* const* d_in, const int* in_sizes, int n_in,
                              void* d_out, int out_size) {
    const void* xidx = d_in[0];
    const void* ei = d_in[1];
    const float* emb = (const float*)d_in[2];
    const float* W1 = (const float*)d_in[3];
    const float* a_src1 = (const float*)d_in[4];
    const float* a_dst1 = (const float*)d_in[5];
    const float* b1 = (const float*)d_in[6];
    const float* W2 = (const float*)d_in[7];
    const float* a_src2 = (const float*)d_in[8];
    const float* a_dst2 = (const float*)d_in[9];
    const float* b2 = (const float*)d_in[10];
    float* out = (float*)d_out;

    int n = in_sizes[0];
    int e = in_sizes[1] / 2;

    int nb256 = (n + 255) / 256;
    int eb256 = (e + 255) / 256;
    int gb = (n + 63) / 64;
    int sb = (e + 1023) / 1024;     // scatter blocks: 256 thr x 4 edges
    int cb = (n + 7) / 8;           // emb-convert blocks
    int g1b = (n + 15) / 16;        // gather1: 16 nodes/block (2/warp)
    int g2b = (n + 31) / 32;        // gather2: 32 nodes/block (4/warp)

    k_conv<<<nb256 + cb + eb256, 256>>>(xidx, W1, W2, emb, ei, n, e, nb256, cb);
    k_scan<<<nb256, 256>>>(n, e);

    k_gemm<1><<<gb + sb, 256>>>(a_src1, a_dst1, n, gb, sb, e);
    k_gather1<<<g1b, 256>>>(b1, n);

    k_gemm<2><<<gb, 256>>>(a_src2, a_dst2, n, gb, 0, 0);
    k_gather2<<<g2b, 256>>>(b2, out, n);
}

// round 16
// speedup vs baseline: 1.1705x; 1.0018x over previous
#include <cuda_runtime.h>
#include <cuda_bf16.h>
#include <cuda_fp16.h>
#include <math.h>

#define MAXN 100000
#define MAXE 1600000

// ---------------- device scratch ----------------
__device__ __align__(16) uint2 g_embh[MAXN * 32];  // gathered emb rows, fp16
__device__ __align__(16) uint4 g_h1h[MAXN * 16];   // layer1 features (128 halves/node)
__device__ __align__(16) uint4 g_x2h[MAXN * 16];   // layer1 output fp16 (128/node)
__device__ __align__(16) uint4 g_h2h[MAXN * 8];    // layer2 features (64 halves/node)
__device__ __align__(16) __half g_w1t[128 * 128];  // W1^T fp16 (n-major)
__device__ __align__(16) __half g_w2t[64 * 128];   // W2^T fp16 (n-major)
// product-form softmax weights: (exp(v), exp(0.2 v)) pairs
__device__ float2 g_es1[MAXN * 4];
__device__ float2 g_ed1[MAXN * 4];
__device__ float2 g_es2[MAXN];
__device__ float2 g_ed2[MAXN];
__device__ int   g_srcb[MAXE];
__device__ int   g_dstb[MAXE];
__device__ int   g_deg[MAXN];         // zeroed by k_scan after reading (replay-safe)
__device__ int   g_off[MAXN + 1];
__device__ int   g_cur[MAXN];
__device__ int   g_csr[MAXE];
__device__ unsigned long long g_lb[512];

__device__ __forceinline__ bool sniff64(const int* xw) { return xw[1] == 0; }

// 16B-chunk swizzle: row-local XOR keeps ldmatrix column reads conflict-free.
__device__ __forceinline__ int swz(int row, int ch) {
    return (row * 16 + (ch ^ (row & 15))) << 4;   // byte offset
}

__device__ __forceinline__ void ldsm4(unsigned& r0, unsigned& r1,
                                      unsigned& r2, unsigned& r3, unsigned addr) {
    asm volatile("ldmatrix.sync.aligned.m8n8.x4.shared.b16 {%0,%1,%2,%3}, [%4];"
                 : "=r"(r0), "=r"(r1), "=r"(r2), "=r"(r3) : "r"(addr));
}
__device__ __forceinline__ void mma16816(float* c, unsigned a0, unsigned a1,
                                         unsigned a2, unsigned a3,
                                         unsigned b0, unsigned b1) {
    asm volatile(
        "mma.sync.aligned.m16n8k16.row.col.f32.f16.f16.f32 "
        "{%0,%1,%2,%3}, {%4,%5,%6,%7}, {%8,%9}, {%0,%1,%2,%3};"
        : "+f"(c[0]), "+f"(c[1]), "+f"(c[2]), "+f"(c[3])
        : "r"(a0), "r"(a1), "r"(a2), "r"(a3), "r"(b0), "r"(b1));
}
__device__ __forceinline__ void cpa16(unsigned dst, const void* src) {
    asm volatile("cp.async.cg.shared.global [%0], [%1], 16;"
                 :: "r"(dst), "l"(src));
}
__device__ __forceinline__ void cpa_wait() {
    asm volatile("cp.async.commit_group;");
    asm volatile("cp.async.wait_group 0;" ::: "memory");
}
__device__ __forceinline__ float2 exp_pair(float v) {
    return make_float2(__expf(v), __expf(0.2f * v));
}

// ------- conversion kernel: 2 block roles (W conv + lb reset | ei conv + degree) ----
__global__ void k_conv(const void* __restrict__ xidx,
                       const float* __restrict__ W1,
                       const float* __restrict__ W2,
                       const void* __restrict__ ei,
                       int n, int e, int nb) {
    int b = blockIdx.x;
    if (b < nb) {
        int i = b * 256 + threadIdx.x;
        if (i < 512) g_lb[i] = 0ull;
        if (i < 128 * 128) {
            int nn = i >> 7, k = i & 127;
            g_w1t[i] = __float2half(W1[k * 128 + nn]);
        }
        if (i < 64 * 128) {
            int nn = i >> 7, k = i & 127;
            g_w2t[i] = __float2half(W2[k * 64 + nn]);
        }
        return;
    }
    int i = (b - nb) * 256 + threadIdx.x;
    if (i >= e) return;
    bool is64 = sniff64((const int*)xidx);
    int s, d;
    if (is64) {
        s = (int)((const long long*)ei)[i];
        d = (int)((const long long*)ei)[(long long)e + i];
    } else {
        s = ((const int*)ei)[i];
        d = ((const int*)ei)[e + i];
    }
    g_srcb[i] = s;
    g_dstb[i] = d;
    atomicAdd(&g_deg[d], 1);
}

// ---------------- scan launch: scan blocks + emb-gather blocks overlapped ----------
// Blocks [0, nbs): decoupled-lookback scan. Blocks [nbs, ...): emb gather->fp16
// (independent DRAM work that fills SMs left idle by the scan's lookback waits).
__global__ void k_scan(const void* __restrict__ xidx,
                       const float* __restrict__ emb,
                       int n, int etot, int nbs) {
    if ((int)blockIdx.x >= nbs) {
        int node = (blockIdx.x - nbs) * 8 + (threadIdx.x >> 5);
        int lane = threadIdx.x & 31;
        if (node >= n) return;
        bool is64 = sniff64((const int*)xidx);
        long long g = is64 ? ((const long long*)xidx)[node]
                           : (long long)((const int*)xidx)[node];
        float4 x = ((const float4*)emb)[g * 32 + lane];
        __half2 h0 = __float22half2_rn(make_float2(x.x, x.y));
        __half2 h1 = __float22half2_rn(make_float2(x.z, x.w));
        g_embh[node * 32 + lane] = make_uint2(*(unsigned*)&h0, *(unsigned*)&h1);
        return;
    }
    __shared__ int s[256];
    __shared__ int s_prefix;
    int tid = threadIdx.x;
    int b = blockIdx.x;
    int i = b * 256 + tid;
    int v = (i < n) ? g_deg[i] : 0;
    s[tid] = v;
    __syncthreads();
    for (int o = 1; o < 256; o <<= 1) {
        int t = 0;
        if (tid >= o) t = s[tid - o];
        __syncthreads();
        s[tid] += t;
        __syncthreads();
    }
    int incl = s[tid];
    int agg = s[255];

    if (tid < 32) {
        if (tid == 0) {
            unsigned long long pub = (b == 0)
                ? ((2ull << 32) | (unsigned)agg)
                : ((1ull << 32) | (unsigned)agg);
            __threadfence();
            atomicExch(&g_lb[b], pub);
        }
        int ex = 0;
        if (b > 0) {
            int p = b - 1;
            while (true) {
                int idx = p - (int)tid;
                unsigned long long st = (idx >= 0) ? atomicAdd(&g_lb[idx], 0ull)
                                                   : (2ull << 32);
                unsigned flag = (unsigned)(st >> 32);
                if (__any_sync(0xffffffffu, flag == 0u)) continue;
                unsigned m2 = __ballot_sync(0xffffffffu, flag == 2u);
                int contrib;
                if (m2) {
                    int L = __ffs(m2) - 1;
                    contrib = ((int)tid <= L) ? (int)(unsigned)st : 0;
                } else {
                    contrib = (int)(unsigned)st;
                }
#pragma unroll
                for (int o = 16; o > 0; o >>= 1)
                    contrib += __shfl_xor_sync(0xffffffffu, contrib, o);
                ex += contrib;
                if (m2) break;
                p -= 32;
            }
            if (tid == 0) {
                __threadfence();
                atomicExch(&g_lb[b], (2ull << 32) | (unsigned)(ex + agg));
            }
        }
        if (tid == 0) s_prefix = ex;
    }
    __syncthreads();
    int ex = s_prefix;
    if (i < n) {
        int o = ex + incl - v;
        g_off[i] = o;
        g_cur[i] = o;
        g_deg[i] = 0;
        if (i == n - 1) g_off[n] = etot;
    }
}

// ---------------- tensor-core GEMM, cp.async staging, fragment-direct epilogue -----
template <int LAYER>
__global__ void __launch_bounds__(256, 4) k_gemm(const float* __restrict__ asrc,
                                                 const float* __restrict__ adst,
                                                 int n, int gb, int sb, int e) {
    int gemm_idx = blockIdx.x;
    if (LAYER == 1) {
        int bid = blockIdx.x;
        int mn = (gb < sb) ? gb : sb;
        int both = 2 * mn;
        bool isc;
        int ridx;
        if (bid < both) {
            isc = (bid & 1);
            ridx = bid >> 1;
        } else if (gb >= sb) {
            isc = false;
            ridx = bid - both + mn;
        } else {
            isc = true;
            ridx = bid - both + mn;
        }
        if (isc) {
            int start = ridx * 1024 + threadIdx.x;
#pragma unroll
            for (int k = 0; k < 4; k++) {
                int i = start + k * 256;
                if (i < e) {
                    int pos = atomicAdd(&g_cur[g_dstb[i]], 1);
                    g_csr[pos] = g_srcb[i];
                }
            }
            return;
        }
        gemm_idx = ridx;
    }

    constexpr int COLS = (LAYER == 1) ? 128 : 64;
    constexpr int NT2 = COLS / 16;          // n-tiles per warp: 8 / 4
    constexpr int SBYTES = 16384 + COLS * 256;

    __shared__ __align__(16) char sbuf[SBYTES];
    char* Ab = sbuf;
    char* Bb = sbuf + 16384;

    const int tid = threadIdx.x;
    const int lane = tid & 31;
    const int wid = tid >> 5;
    const int base = gemm_idx * 64;

    unsigned a_u = (unsigned)__cvta_generic_to_shared(Ab);
    unsigned b_u = (unsigned)__cvta_generic_to_shared(Bb);

    // ---- stage A (fp16 node rows, cp.async) ----
    const uint4* Asrc = (LAYER == 1) ? (const uint4*)g_embh : g_x2h;
#pragma unroll 4
    for (int idx = tid; idx < 64 * 16; idx += 256) {
        int r = idx >> 4, ch = idx & 15;
        int node = base + r;
        if (node < n) cpa16(a_u + swz(r, ch), Asrc + node * 16 + ch);
        else *(uint4*)(Ab + swz(r, ch)) = make_uint4(0, 0, 0, 0);
    }
    // ---- stage B = W^T (cp.async) ----
    {
        const uint4* Wt = (const uint4*)((LAYER == 1) ? g_w1t : g_w2t);
#pragma unroll 4
        for (int idx = tid; idx < COLS * 16; idx += 256) {
            int r = idx >> 4, ch = idx & 15;
            cpa16(b_u + swz(r, ch), Wt + r * 16 + ch);
        }
    }
    cpa_wait();
    __syncthreads();

    // ---- mma mainloop: warp = m16 (mw) x n-half (nh) ----
    const int mw = wid >> 1;
    const int nh = wid & 1;
    const int m0 = mw * 16;

    float c[NT2][4];
#pragma unroll
    for (int j = 0; j < NT2; j++)
#pragma unroll
        for (int q = 0; q < 4; q++) c[j][q] = 0.f;

    const int tl = lane >> 3;
    const int rr = lane & 7;

#pragma unroll
    for (int s = 0; s < 8; s++) {
        int chunk = 2 * s + (tl >> 1);
        unsigned a0, a1, a2, a3;
        ldsm4(a0, a1, a2, a3, a_u + swz(m0 + (tl & 1) * 8 + rr, chunk));
#pragma unroll
        for (int t = 0; t < NT2 / 2; t++) {
            int brow = nh * (NT2 * 8) + t * 16;
            unsigned r0, r1, r2, r3;
            ldsm4(r0, r1, r2, r3, b_u + swz(brow + (tl & 1) * 8 + rr, chunk));
            mma16816(c[2 * t], a0, a1, a2, a3, r0, r2);
            mma16816(c[2 * t + 1], a0, a1, a2, a3, r1, r3);
        }
    }

    // ---- fragment-direct epilogue ----
    const int g = lane >> 2;
    const int tg = lane & 3;
    const int colbase = nh * (NT2 * 8);     // 0/64 (L1), 0/32 (L2)
    const int node0 = base + m0 + g;
    const int node1 = node0 + 8;

    if (LAYER == 1) {
        float s0a = 0.f, s0b = 0.f, d0a = 0.f, d0b = 0.f;   // row g
        float s1a = 0.f, s1b = 0.f, d1a = 0.f, d1b = 0.f;   // row g+8
#pragma unroll
        for (int j = 0; j < 8; j++) {
            int col = colbase + j * 8 + 2 * tg;
            float2 as = __ldg((const float2*)(asrc + col));
            float2 ad = __ldg((const float2*)(adst + col));
            float ps0 = c[j][0] * as.x + c[j][1] * as.y;
            float pd0 = c[j][0] * ad.x + c[j][1] * ad.y;
            float ps1 = c[j][2] * as.x + c[j][3] * as.y;
            float pd1 = c[j][2] * ad.x + c[j][3] * ad.y;
            if (j < 4) { s0a += ps0; d0a += pd0; s1a += ps1; d1a += pd1; }
            else       { s0b += ps0; d0b += pd0; s1b += ps1; d1b += pd1; }
        }
#pragma unroll
        for (int o = 1; o < 4; o <<= 1) {
            s0a += __shfl_xor_sync(0xffffffffu, s0a, o);
            s0b += __shfl_xor_sync(0xffffffffu, s0b, o);
            d0a += __shfl_xor_sync(0xffffffffu, d0a, o);
            d0b += __shfl_xor_sync(0xffffffffu, d0b, o);
            s1a += __shfl_xor_sync(0xffffffffu, s1a, o);
            s1b += __shfl_xor_sync(0xffffffffu, s1b, o);
            d1a += __shfl_xor_sync(0xffffffffu, d1a, o);
            d1b += __shfl_xor_sync(0xffffffffu, d1b, o);
        }
        int h0i = 2 * nh, h1i = 2 * nh + 1;
        if (tg == 0) {
            if (node0 < n) {
                g_es1[node0 * 4 + h0i] = exp_pair(s0a);
                g_es1[node0 * 4 + h1i] = exp_pair(s0b);
                g_ed1[node0 * 4 + h0i] = exp_pair(d0a);
                g_ed1[node0 * 4 + h1i] = exp_pair(d0b);
            }
            if (node1 < n) {
                g_es1[node1 * 4 + h0i] = exp_pair(s1a);
                g_es1[node1 * 4 + h1i] = exp_pair(s1b);
                g_ed1[node1 * 4 + h0i] = exp_pair(d1a);
                g_ed1[node1 * 4 + h1i] = exp_pair(d1b);
            }
        }
        unsigned* H = (unsigned*)g_h1h;     // node*64 unsigneds (half2 each)
#pragma unroll
        for (int j = 0; j < 8; j++) {
            int ci = (colbase >> 1) + j * 4 + tg;
            __half2 h0 = __float22half2_rn(make_float2(c[j][0], c[j][1]));
            __half2 h1 = __float22half2_rn(make_float2(c[j][2], c[j][3]));
            if (node0 < n) H[node0 * 64 + ci] = *(unsigned*)&h0;
            if (node1 < n) H[node1 * 64 + ci] = *(unsigned*)&h1;
        }
    } else {
        float s0 = 0.f, d0 = 0.f, s1 = 0.f, d1 = 0.f;
#pragma unroll
        for (int j = 0; j < 4; j++) {
            int col = colbase + j * 8 + 2 * tg;
            float2 as = __ldg((const float2*)(asrc + col));
            float2 ad = __ldg((const float2*)(adst + col));
            s0 += c[j][0] * as.x + c[j][1] * as.y;
            d0 += c[j][0] * ad.x + c[j][1] * ad.y;
            s1 += c[j][2] * as.x + c[j][3] * as.y;
            d1 += c[j][2] * ad.x + c[j][3] * ad.y;
        }
#pragma unroll
        for (int o = 1; o < 4; o <<= 1) {
            s0 += __shfl_xor_sync(0xffffffffu, s0, o);
            d0 += __shfl_xor_sync(0xffffffffu, d0, o);
            s1 += __shfl_xor_sync(0xffffffffu, s1, o);
            d1 += __shfl_xor_sync(0xffffffffu, d1, o);
        }
        unsigned* H = (unsigned*)g_h2h;     // node*32 unsigneds
#pragma unroll
        for (int j = 0; j < 4; j++) {
            int ci = (colbase >> 1) + j * 4 + tg;
            __half2 h0 = __float22half2_rn(make_float2(c[j][0], c[j][1]));
            __half2 h1 = __float22half2_rn(make_float2(c[j][2], c[j][3]));
            if (node0 < n) H[node0 * 32 + ci] = *(unsigned*)&h0;
            if (node1 < n) H[node1 * 32 + ci] = *(unsigned*)&h1;
        }
        // combine the two warp-half partials via smem (overlay on staging buffer)
        __syncthreads();
        float* sC = (float*)sbuf;             // [64][4]
        if (tg == 0) {
            int r0 = m0 + g, r1 = m0 + g + 8;
            sC[r0 * 4 + nh] = s0;
            sC[r0 * 4 + 2 + nh] = d0;
            sC[r1 * 4 + nh] = s1;
            sC[r1 * 4 + 2 + nh] = d1;
        }
        __syncthreads();
        if (tid < 64) {
            int node = base + tid;
            if (node < n) {
                float s = sC[tid * 4] + sC[tid * 4 + 1];
                float d = sC[tid * 4 + 2] + sC[tid * 4 + 3];
                g_es2[node] = exp_pair(s);
                g_ed2[node] = exp_pair(d);
            }
        }
    }
}

// ---- fused gather layer 1: 4 nodes/warp (8 lanes each, 16 cols/lane) ----
__global__ void k_gather1(const float* __restrict__ b1, int n) {
    int warp = (blockIdx.x * blockDim.x + threadIdx.x) >> 5;
    int lane = threadIdx.x & 31;
    int sl = lane & 7;                     // sublane within node
    int node = warp * 4 + (lane >> 3);
    if (node >= n) return;
    int head = sl >> 1;                    // 2 lanes per head (32 cols)

    float2 ed = g_ed1[node * 4 + head];

    // self loop
    float2 e0 = g_es1[node * 4 + head];
    float p = e0.x * ed.x, q = e0.y * ed.y;
    float w = (p > 1.f) ? p : q;
    const uint4* H = g_h1h;
    uint4 pk0 = H[node * 16 + sl * 2];
    uint4 pk1 = H[node * 16 + sl * 2 + 1];
    float acc[16];
    {
        float2 t;
        t = __half22float2(*(const __half2*)&pk0.x); acc[0] = w * t.x; acc[1] = w * t.y;
        t = __half22float2(*(const __half2*)&pk0.y); acc[2] = w * t.x; acc[3] = w * t.y;
        t = __half22float2(*(const __half2*)&pk0.z); acc[4] = w * t.x; acc[5] = w * t.y;
        t = __half22float2(*(const __half2*)&pk0.w); acc[6] = w * t.x; acc[7] = w * t.y;
        t = __half22float2(*(const __half2*)&pk1.x); acc[8] = w * t.x; acc[9] = w * t.y;
        t = __half22float2(*(const __half2*)&pk1.y); acc[10] = w * t.x; acc[11] = w * t.y;
        t = __half22float2(*(const __half2*)&pk1.z); acc[12] = w * t.x; acc[13] = w * t.y;
        t = __half22float2(*(const __half2*)&pk1.w); acc[14] = w * t.x; acc[15] = w * t.y;
    }
    float wsum = w;

    int i = g_off[node];
    int iend = g_off[node + 1];
    for (; i < iend; i++) {
        int src = g_csr[i];
        float2 es = g_es1[src * 4 + head];
        float pp = es.x * ed.x, qq = es.y * ed.y;
        float ww = (pp > 1.f) ? pp : qq;
        uint4 q0 = H[src * 16 + sl * 2];
        uint4 q1 = H[src * 16 + sl * 2 + 1];
        float2 t;
        t = __half22float2(*(const __half2*)&q0.x); acc[0] += ww * t.x; acc[1] += ww * t.y;
        t = __half22float2(*(const __half2*)&q0.y); acc[2] += ww * t.x; acc[3] += ww * t.y;
        t = __half22float2(*(const __half2*)&q0.z); acc[4] += ww * t.x; acc[5] += ww * t.y;
        t = __half22float2(*(const __half2*)&q0.w); acc[6] += ww * t.x; acc[7] += ww * t.y;
        t = __half22float2(*(const __half2*)&q1.x); acc[8] += ww * t.x; acc[9] += ww * t.y;
        t = __half22float2(*(const __half2*)&q1.y); acc[10] += ww * t.x; acc[11] += ww * t.y;
        t = __half22float2(*(const __half2*)&q1.z); acc[12] += ww * t.x; acc[13] += ww * t.y;
        t = __half22float2(*(const __half2*)&q1.w); acc[14] += ww * t.x; acc[15] += ww * t.y;
        wsum += ww;
    }
    float inv = 1.f / wsum;
    unsigned outw[8];
#pragma unroll
    for (int j = 0; j < 8; j++) {
        float4 bb = ((const float4*)b1)[sl * 4 + j / 2 * 2 + (j & 1)];
        // simpler: compute bias index directly below
    }
    // bias: cols sl*16 .. sl*16+15 -> float4 idx sl*4 .. sl*4+3
    const float4* B4 = (const float4*)b1;
#pragma unroll
    for (int j = 0; j < 4; j++) {
        float4 bb = B4[sl * 4 + j];
        float o0 = acc[j * 4 + 0] * inv + bb.x;
        float o1 = acc[j * 4 + 1] * inv + bb.y;
        float o2 = acc[j * 4 + 2] * inv + bb.z;
        float o3 = acc[j * 4 + 3] * inv + bb.w;
        o0 = (o0 > 0.f) ? o0 : expm1f(o0);
        o1 = (o1 > 0.f) ? o1 : expm1f(o1);
        o2 = (o2 > 0.f) ? o2 : expm1f(o2);
        o3 = (o3 > 0.f) ? o3 : expm1f(o3);
        __half2 h0 = __float22half2_rn(make_float2(o0, o1));
        __half2 h1 = __float22half2_rn(make_float2(o2, o3));
        outw[j * 2] = *(unsigned*)&h0;
        outw[j * 2 + 1] = *(unsigned*)&h1;
    }
    g_x2h[node * 16 + sl * 2] = make_uint4(outw[0], outw[1], outw[2], outw[3]);
    g_x2h[node * 16 + sl * 2 + 1] = make_uint4(outw[4], outw[5], outw[6], outw[7]);
}

// ---- fused gather layer 2: 8 nodes/warp (4 lanes each, 16 cols/lane) ----
__global__ void k_gather2(const float* __restrict__ b2, float* __restrict__ out, int n) {
    int warp = (blockIdx.x * blockDim.x + threadIdx.x) >> 5;
    int lane = threadIdx.x & 31;
    int sl = lane & 3;                     // sublane within node
    int node = warp * 8 + (lane >> 2);
    if (node >= n) return;

    float2 ed = g_ed2[node];

    float2 e0 = g_es2[node];
    float p = e0.x * ed.x, q = e0.y * ed.y;
    float w = (p > 1.f) ? p : q;
    const uint4* H = g_h2h;
    uint4 pk0 = H[node * 8 + sl * 2];
    uint4 pk1 = H[node * 8 + sl * 2 + 1];
    float acc[16];
    {
        float2 t;
        t = __half22float2(*(const __half2*)&pk0.x); acc[0] = w * t.x; acc[1] = w * t.y;
        t = __half22float2(*(const __half2*)&pk0.y); acc[2] = w * t.x; acc[3] = w * t.y;
        t = __half22float2(*(const __half2*)&pk0.z); acc[4] = w * t.x; acc[5] = w * t.y;
        t = __half22float2(*(const __half2*)&pk0.w); acc[6] = w * t.x; acc[7] = w * t.y;
        t = __half22float2(*(const __half2*)&pk1.x); acc[8] = w * t.x; acc[9] = w * t.y;
        t = __half22float2(*(const __half2*)&pk1.y); acc[10] = w * t.x; acc[11] = w * t.y;
        t = __half22float2(*(const __half2*)&pk1.z); acc[12] = w * t.x; acc[13] = w * t.y;
        t = __half22float2(*(const __half2*)&pk1.w); acc[14] = w * t.x; acc[15] = w * t.y;
    }
    float wsum = w;

    int i = g_off[node];
    int iend = g_off[node + 1];
    for (; i < iend; i++) {
        int src = g_csr[i];
        float2 es = g_es2[src];
        float pp = es.x * ed.x, qq = es.y * ed.y;
        float ww = (pp > 1.f) ? pp : qq;
        uint4 q0 = H[src * 8 + sl * 2];
        uint4 q1 = H[src * 8 + sl * 2 + 1];
        float2 t;
        t = __half22float2(*(const __half2*)&q0.x); acc[0] += ww * t.x; acc[1] += ww * t.y;
        t = __half22float2(*(const __half2*)&q0.y); acc[2] += ww * t.x; acc[3] += ww * t.y;
        t = __half22float2(*(const __half2*)&q0.z); acc[4] += ww * t.x; acc[5] += ww * t.y;
        t = __half22float2(*(const __half2*)&q0.w); acc[6] += ww * t.x; acc[7] += ww * t.y;
        t = __half22float2(*(const __half2*)&q1.x); acc[8] += ww * t.x; acc[9] += ww * t.y;
        t = __half22float2(*(const __half2*)&q1.y); acc[10] += ww * t.x; acc[11] += ww * t.y;
        t = __half22float2(*(const __half2*)&q1.z); acc[12] += ww * t.x; acc[13] += ww * t.y;
        t = __half22float2(*(const __half2*)&q1.w); acc[14] += ww * t.x; acc[15] += ww * t.y;
        wsum += ww;
    }
    float inv = 1.f / wsum;
    const float4* B4 = (const float4*)b2;
#pragma unroll
    for (int j = 0; j < 4; j++) {
        float4 bb = B4[sl * 4 + j];
        float4 r = make_float4(acc[j * 4 + 0] * inv + bb.x,
                               acc[j * 4 + 1] * inv + bb.y,
                               acc[j * 4 + 2] * inv + bb.z,
                               acc[j * 4 + 3] * inv + bb.w);
        ((float4*)out)[node * 16 + sl * 4 + j] = r;
    }
}

// ---------------- launch ----------------
extern "C" void kernel_launch(void* const* d_in, const int* in_sizes, int n_in,
                              void* d_out, int out_size) {
    const void* xidx = d_in[0];
    const void* ei = d_in[1];
    const float* emb = (const float*)d_in[2];
    const float* W1 = (const float*)d_in[3];
    const float* a_src1 = (const float*)d_in[4];
    const float* a_dst1 = (const float*)d_in[5];
    const float* b1 = (const float*)d_in[6];
    const float* W2 = (const float*)d_in[7];
    const float* a_src2 = (const float*)d_in[8];
    const float* a_dst2 = (const float*)d_in[9];
    const float* b2 = (const float*)d_in[10];
    float* out = (float*)d_out;

    int n = in_sizes[0];
    int e = in_sizes[1] / 2;

    int nb256 = (n + 255) / 256;
    int eb256 = (e + 255) / 256;
    int gb = (n + 63) / 64;
    int sb = (e + 1023) / 1024;     // scatter blocks
    int cb = (n + 7) / 8;           // emb-convert blocks
    int g1b = (n + 31) / 32;        // gather1: 32 nodes/block (4/warp)
    int g2b = (n + 63) / 64;        // gather2: 64 nodes/block (8/warp)

    k_conv<<<nb256 + eb256, 256>>>(xidx, W1, W2, ei, n, e, nb256);
    k_scan<<<nb256 + cb, 256>>>(xidx, emb, n, e, nb256);

    k_gemm<1><<<gb + sb, 256>>>(a_src1, a_dst1, n, gb, sb, e);
    k_gather1<<<g1b, 256>>>(b1, n);

    k_gemm<2><<<gb, 256>>>(a_src2, a_dst2, n, gb, 0, 0);
    k_gather2<<<g2b, 256>>>(b2, out, n);
}